// round 12
// baseline (speedup 1.0000x reference)
#include <cuda_runtime.h>
#include <cuda_fp16.h>
#include <cuda_bf16.h>
#include <math.h>
#include <float.h>

#define NB 144          // total blocks (1 CTA/SM)
#define GROUPS 4        // independent groups (L2-resident constraint: <= 4)
#define GNB 36          // blocks per group
#define ANB 18          // Sinkhorn subgroup (blocks 0..17)
#define SPG 8           // timesteps per group
#define NT 1024         // threads per block
#define N_ 4096
#define S_ 32
#define D_ 128
#define MAXP 4352       // worst-case padded dim (multiple of 256)
#define ITS 20
#define EPSK 1e-6f
#define LDH 72
#define SMEM_BYTES 73728

// ---------------- persistent scratch ----------------
__device__ __align__(16) __nv_bfloat16 g_Xh[(size_t)S_ * N_ * D_];
__device__ __align__(16) __nv_bfloat16 g_Xl[(size_t)S_ * N_ * D_];
__device__ float  g_nrm[S_ * N_];
__device__ __align__(16) float  g_M [(size_t)GROUPS * 2 * MAXP * MAXP];  // double-buffered
__device__ __align__(16) __half g_K [(size_t)GROUPS * MAXP * MAXP];
__device__ __align__(16) __half g_KT[(size_t)GROUPS * MAXP * MAXP];
__device__ __align__(16) float  g_u [GROUPS][MAXP];
__device__ __align__(16) float  g_bv[GROUPS][MAXP];
__device__ int    g_perm[GROUPS][N_];
__device__ int    g_ntA [GROUPS];
__device__ float  g_pA  [GROUPS];
__device__ float  g_pmax[GROUPS][ANB];
__device__ double g_psum[GROUPS][ANB];
__device__ double g_pres[GROUPS][GNB];
__device__ double g_res [S_];
__device__ unsigned long long g_barCnt [GROUPS * 16];   // full barrier (36 arrivals)
__device__ unsigned long long g_barCntA[GROUPS * 16];   // A-subgroup barrier (18 arrivals)
__device__ unsigned long long g_doneCnt;

// ---------------- barriers: monotonic 64-bit counters ----------------
__device__ __forceinline__ void gbar_sync(unsigned long long* cnt, unsigned long long tgt) {
    __syncthreads();
    if (threadIdx.x == 0) {
        __threadfence();
        atomicAdd(cnt, 1ULL);
        while (*(volatile unsigned long long*)cnt < tgt) { __nanosleep(32); }
        __threadfence();
    }
    __syncthreads();
}
#define GBAR() do { ++barKF; gbar_sync(cntF, barBaseF + (unsigned long long)barKF * GNB); } while (0)
#define ABAR() do { ++barKA; gbar_sync(cntA, barBaseA + (unsigned long long)barKA * ANB); } while (0)

// ---------------- FFMA-only expf ----------------
__device__ __forceinline__ float fast_exp(float x) {
    const float L2E = 1.4426950408889634f;
    float y = fmaf(x, L2E, 12582912.0f);
    int   n = __float_as_int(y) - 0x4B400000;
    float r = y - 12582912.0f;
    float f = fmaf(x, L2E, -r);
    float p =        1.540353040e-4f;
    p = fmaf(p, f,   1.333355815e-3f);
    p = fmaf(p, f,   9.618129107e-3f);
    p = fmaf(p, f,   5.550410866e-2f);
    p = fmaf(p, f,   2.402265070e-1f);
    p = fmaf(p, f,   6.931471806e-1f);
    p = fmaf(p, f,   1.0f);
    return p * __int_as_float((n + 127) << 23);
}

__device__ __forceinline__ float warpMaxF(float v) {
    #pragma unroll
    for (int o = 16; o; o >>= 1) v = fmaxf(v, __shfl_down_sync(0xffffffffu, v, o));
    return v;
}
__device__ __forceinline__ float warpSumF(float v) {
    #pragma unroll
    for (int o = 16; o; o >>= 1) v += __shfl_down_sync(0xffffffffu, v, o);
    return v;
}
__device__ __forceinline__ double warpSumD(double v) {
    #pragma unroll
    for (int o = 16; o; o >>= 1) v += __shfl_down_sync(0xffffffffu, v, o);
    return v;
}
__device__ __forceinline__ void warpSum4F(float& v0, float& v1, float& v2, float& v3) {
    #pragma unroll
    for (int o = 16; o; o >>= 1) {
        v0 += __shfl_down_sync(0xffffffffu, v0, o);
        v1 += __shfl_down_sync(0xffffffffu, v1, o);
        v2 += __shfl_down_sync(0xffffffffu, v2, o);
        v3 += __shfl_down_sync(0xffffffffu, v3, o);
    }
}

// ---------------- mma.sync m16n8k16 bf16 (fp32 accum) ----------------
__device__ __forceinline__ void mma16816(float& c0, float& c1, float& c2, float& c3,
                                         unsigned a0, unsigned a1, unsigned a2, unsigned a3,
                                         unsigned b0, unsigned b1) {
    asm volatile("mma.sync.aligned.m16n8k16.row.col.f32.bf16.bf16.f32 "
        "{%0,%1,%2,%3}, {%4,%5,%6,%7}, {%8,%9}, {%0,%1,%2,%3};"
        : "+f"(c0), "+f"(c1), "+f"(c2), "+f"(c3)
        : "r"(a0), "r"(a1), "r"(a2), "r"(a3), "r"(b0), "r"(b1));
}

// ---------------- distance GEMM for one timestep (executed by 18 B-blocks) ----------------
// block tile 128x128, 32 warps (m16n32 per warp), split-precision bf16 via mma.sync
__device__ void gemm_step(const __nv_bfloat16* Xhs, const __nv_bfloat16* Xls,
                          const float* nrm, float* Mg,
                          int nt, int nc, int CPP, int lbB,
                          int tid, int lane, int wid,
                          __nv_bfloat16* Ah, __nv_bfloat16* Al,
                          __nv_bfloat16* Bh, __nv_bfloat16* Bl,
                          float* s_f, double* s_d,
                          float* out_pmax, double* out_psum)
{
    const int tilesI = (nt + 127) >> 7;
    const int tilesJ = (nc + 127) >> 7;
    const int nTiles = tilesI * tilesJ;
    const int wm = wid >> 2;
    const int wn = wid & 3;
    const int ldrow = tid >> 3;
    const int ldch  = tid & 7;
    float  lmax = -FLT_MAX;
    double lsum = 0.0;

    for (int tile = lbB; tile < nTiles; tile += ANB) {
        int ti = tile / tilesJ, tj = tile - ti * tilesJ;
        int i0 = ti << 7, j0 = tj << 7;

        float acc[4][4];
        #pragma unroll
        for (int q = 0; q < 4; q++)
            #pragma unroll
            for (int c = 0; c < 4; c++) acc[q][c] = 0.0f;

        for (int kb = 0; kb < D_; kb += 64) {
            __syncthreads();
            {
                int ar = i0 + ldrow; if (ar >= nt) ar = nt - 1;
                int br = j0 + ldrow; if (br >= nc) br = nc - 1;
                size_t aoff = (size_t)ar * D_ + kb + ldch * 8;
                size_t boff = (size_t)(nt + br) * D_ + kb + ldch * 8;
                int sm = ldrow * LDH + ldch * 8;
                *(uint4*)&Ah[sm] = *(const uint4*)(Xhs + aoff);
                *(uint4*)&Al[sm] = *(const uint4*)(Xls + aoff);
                *(uint4*)&Bh[sm] = *(const uint4*)(Xhs + boff);
                *(uint4*)&Bl[sm] = *(const uint4*)(Xls + boff);
            }
            __syncthreads();
            #pragma unroll
            for (int ks = 0; ks < 4; ks++) {
                const int arow = wm * 16 + (lane >> 2);
                const int ac   = ks * 16 + (lane & 3) * 2;
                unsigned ah0 = *(const unsigned*)&Ah[arow * LDH + ac];
                unsigned ah1 = *(const unsigned*)&Ah[(arow + 8) * LDH + ac];
                unsigned ah2 = *(const unsigned*)&Ah[arow * LDH + ac + 8];
                unsigned ah3 = *(const unsigned*)&Ah[(arow + 8) * LDH + ac + 8];
                unsigned al0 = *(const unsigned*)&Al[arow * LDH + ac];
                unsigned al1 = *(const unsigned*)&Al[(arow + 8) * LDH + ac];
                unsigned al2 = *(const unsigned*)&Al[arow * LDH + ac + 8];
                unsigned al3 = *(const unsigned*)&Al[(arow + 8) * LDH + ac + 8];
                #pragma unroll
                for (int q = 0; q < 4; q++) {
                    const int bn = wn * 32 + q * 8 + (lane >> 2);
                    unsigned bh0 = *(const unsigned*)&Bh[bn * LDH + ac];
                    unsigned bh1 = *(const unsigned*)&Bh[bn * LDH + ac + 8];
                    unsigned bl0 = *(const unsigned*)&Bl[bn * LDH + ac];
                    unsigned bl1 = *(const unsigned*)&Bl[bn * LDH + ac + 8];
                    mma16816(acc[q][0], acc[q][1], acc[q][2], acc[q][3],
                             ah0, ah1, ah2, ah3, bh0, bh1);
                    mma16816(acc[q][0], acc[q][1], acc[q][2], acc[q][3],
                             ah0, ah1, ah2, ah3, bl0, bl1);
                    mma16816(acc[q][0], acc[q][1], acc[q][2], acc[q][3],
                             al0, al1, al2, al3, bh0, bh1);
                }
            }
        }

        float tsum = 0.0f;
        const int er0 = i0 + wm * 16 + (lane >> 2);
        #pragma unroll
        for (int half = 0; half < 2; half++) {
            const int rr = er0 + half * 8;
            if (rr >= nt) continue;
            const float nx = nrm[rr];
            float* Mrow = Mg + (size_t)rr * CPP;
            #pragma unroll
            for (int q = 0; q < 4; q++) {
                const int cc = j0 + wn * 32 + q * 8 + (lane & 3) * 2;
                const float d0 = acc[q][half * 2 + 0];
                const float d1 = acc[q][half * 2 + 1];
                if (cc + 1 < nc) {
                    float m0 = fmaf(-2.0f, d0, nx + nrm[nt + cc]);
                    float m1 = fmaf(-2.0f, d1, nx + nrm[nt + cc + 1]);
                    *(float2*)(Mrow + cc) = make_float2(m0, m1);
                    lmax = fmaxf(lmax, fmaxf(m0, m1));
                    tsum += m0 + m1;
                } else if (cc < nc) {
                    float m0 = fmaf(-2.0f, d0, nx + nrm[nt + cc]);
                    Mrow[cc] = m0;
                    lmax = fmaxf(lmax, m0);
                    tsum += m0;
                }
            }
        }
        lsum += (double)tsum;
    }
    lmax = warpMaxF(lmax);
    lsum = warpSumD(lsum);
    __syncthreads();
    if (lane == 0) { s_f[wid] = lmax; s_d[wid] = lsum; }
    __syncthreads();
    if (wid == 0) {
        float  m2 = s_f[lane];
        double s2 = s_d[lane];
        m2 = warpMaxF(m2);
        s2 = warpSumD(s2);
        if (lane == 0) { *out_pmax = m2; *out_psum = s2; }
    }
    __syncthreads();
}

// ---------------- 4-row fp16 matvec dot (segment-permuted layout) ----------------
__device__ __forceinline__ void dot4rows(const __half* base, size_t stride, int rb,
                                         const float* shv, int nseg, int lane,
                                         float& s0, float& s1, float& s2, float& s3) {
    const uint4* Kr0 = (const uint4*)(base + (size_t)(rb + 0) * stride);
    const uint4* Kr1 = (const uint4*)(base + (size_t)(rb + 1) * stride);
    const uint4* Kr2 = (const uint4*)(base + (size_t)(rb + 2) * stride);
    const uint4* Kr3 = (const uint4*)(base + (size_t)(rb + 3) * stride);
    float a0 = 0, a1 = 0, a2 = 0, a3 = 0;
    float b0 = 0, b1 = 0, b2 = 0, b3 = 0;
    for (int sg = 0; sg < nseg; sg++) {
        uint4 k0 = __ldcg(Kr0 + sg * 32 + lane);
        uint4 k1 = __ldcg(Kr1 + sg * 32 + lane);
        uint4 k2 = __ldcg(Kr2 + sg * 32 + lane);
        uint4 k3 = __ldcg(Kr3 + sg * 32 + lane);
        float4 u0 = *(const float4*)(shv + sg * 256 + lane * 4);
        float4 u1 = *(const float4*)(shv + sg * 256 + 128 + lane * 4);
        {
            const __half2* h = (const __half2*)&k0;
            float2 p0 = __half22float2(h[0]), p1 = __half22float2(h[1]);
            float2 p2 = __half22float2(h[2]), p3 = __half22float2(h[3]);
            a0 = fmaf(p0.x, u0.x, a0); b0 = fmaf(p0.y, u0.y, b0);
            a0 = fmaf(p1.x, u0.z, a0); b0 = fmaf(p1.y, u0.w, b0);
            a0 = fmaf(p2.x, u1.x, a0); b0 = fmaf(p2.y, u1.y, b0);
            a0 = fmaf(p3.x, u1.z, a0); b0 = fmaf(p3.y, u1.w, b0);
        }
        {
            const __half2* h = (const __half2*)&k1;
            float2 p0 = __half22float2(h[0]), p1 = __half22float2(h[1]);
            float2 p2 = __half22float2(h[2]), p3 = __half22float2(h[3]);
            a1 = fmaf(p0.x, u0.x, a1); b1 = fmaf(p0.y, u0.y, b1);
            a1 = fmaf(p1.x, u0.z, a1); b1 = fmaf(p1.y, u0.w, b1);
            a1 = fmaf(p2.x, u1.x, a1); b1 = fmaf(p2.y, u1.y, b1);
            a1 = fmaf(p3.x, u1.z, a1); b1 = fmaf(p3.y, u1.w, b1);
        }
        {
            const __half2* h = (const __half2*)&k2;
            float2 p0 = __half22float2(h[0]), p1 = __half22float2(h[1]);
            float2 p2 = __half22float2(h[2]), p3 = __half22float2(h[3]);
            a2 = fmaf(p0.x, u0.x, a2); b2 = fmaf(p0.y, u0.y, b2);
            a2 = fmaf(p1.x, u0.z, a2); b2 = fmaf(p1.y, u0.w, b2);
            a2 = fmaf(p2.x, u1.x, a2); b2 = fmaf(p2.y, u1.y, b2);
            a2 = fmaf(p3.x, u1.z, a2); b2 = fmaf(p3.y, u1.w, b2);
        }
        {
            const __half2* h = (const __half2*)&k3;
            float2 p0 = __half22float2(h[0]), p1 = __half22float2(h[1]);
            float2 p2 = __half22float2(h[2]), p3 = __half22float2(h[3]);
            a3 = fmaf(p0.x, u0.x, a3); b3 = fmaf(p0.y, u0.y, b3);
            a3 = fmaf(p1.x, u0.z, a3); b3 = fmaf(p1.y, u0.w, b3);
            a3 = fmaf(p2.x, u1.x, a3); b3 = fmaf(p2.y, u1.y, b3);
            a3 = fmaf(p3.x, u1.z, a3); b3 = fmaf(p3.y, u1.w, b3);
        }
    }
    s0 = a0 + b0; s1 = a1 + b1; s2 = a2 + b2; s3 = a3 + b3;
    warpSum4F(s0, s1, s2, s3);
}

__global__ void __launch_bounds__(NT, 1)
sinkhorn_all(const float* __restrict__ X, const int* __restrict__ T, float* __restrict__ out)
{
    extern __shared__ __align__(16) char smraw[];
    float* sh = (float*)smraw;
    __nv_bfloat16* Ah = (__nv_bfloat16*)smraw;          // 128 x LDH
    __nv_bfloat16* Al = Ah + 128 * LDH;
    __nv_bfloat16* Bh = Al + 128 * LDH;
    __nv_bfloat16* Bl = Bh + 128 * LDH;

    __shared__ float  s_f[32];
    __shared__ double s_d[32];
    __shared__ float  s_delta, s_efflam;

    const int tid  = threadIdx.x;
    const int bid  = blockIdx.x;
    const int lane = tid & 31;
    const int wid  = tid >> 5;
    const int grp  = bid / GNB;
    const int lb   = bid - grp * GNB;
    const bool isA = (lb < ANB);
    const int lbB  = lb - ANB;           // B-block index 0..17
    const int gw   = lb * 32 + wid;      // warp within group (0..1151)
    const int GW   = GNB * 32;
    const int jid  = wid * ANB + lb;     // A-only job id (0..575)

    unsigned long long* cntF = &g_barCnt [grp * 16];
    unsigned long long* cntA = &g_barCntA[grp * 16];
    unsigned long long vF = *(volatile unsigned long long*)cntF;
    unsigned long long vA = *(volatile unsigned long long*)cntA;
    unsigned long long barBaseF = vF - (vF % (unsigned long long)GNB);
    unsigned long long barBaseA = vA - (vA % (unsigned long long)ANB);
    int barKF = 0, barKA = 0;

    unsigned long long doneBase = 0;
    if (bid == 0 && tid == 0) {
        unsigned long long dv = *(volatile unsigned long long*)&g_doneCnt;
        doneBase = dv - (dv % (unsigned long long)NB);
    }

    float*  Mbuf0 = g_M + (size_t)(grp * 2 + 0) * MAXP * MAXP;
    float*  Mbuf1 = g_M + (size_t)(grp * 2 + 1) * MAXP * MAXP;
    __half* Kg  = g_K  + (size_t)grp * MAXP * MAXP;
    __half* KTg = g_KT + (size_t)grp * MAXP * MAXP;
    float*  ug  = g_u [grp];
    float*  bvg = g_bv[grp];
    int*    permg = g_perm[grp];

    // ---------------- A0: stable permutation (per group) ----------------
    if (lb == 0) {
        int* cnt = (int*)sh;
        int base = tid * 4;
        int tv0 = T[base], tv1 = T[base+1], tv2 = T[base+2], tv3 = T[base+3];
        int c = (tv0 > 0) + (tv1 > 0) + (tv2 > 0) + (tv3 > 0);
        cnt[tid] = c;
        __syncthreads();
        for (int off = 1; off < NT; off <<= 1) {
            int vv  = cnt[tid];
            int add = (tid >= off) ? cnt[tid - off] : 0;
            __syncthreads();
            cnt[tid] = vv + add;
            __syncthreads();
        }
        int total = cnt[NT - 1];
        int excl  = cnt[tid] - c;
        int tpos = excl, cpos = total + base - excl;
        if (tv0 > 0) permg[tpos++] = base + 0; else permg[cpos++] = base + 0;
        if (tv1 > 0) permg[tpos++] = base + 1; else permg[cpos++] = base + 1;
        if (tv2 > 0) permg[tpos++] = base + 2; else permg[cpos++] = base + 2;
        if (tv3 > 0) permg[tpos++] = base + 3; else permg[cpos++] = base + 3;
        if (tid == NT - 1) { g_ntA[grp] = total; g_pA[grp] = (float)total / (float)N_; }
    }
    GBAR();

    const int   nt = g_ntA[grp];
    const int   nc = N_ - nt;
    const float p  = g_pA[grp];
    const int   R = nt + 1, C = nc + 1;
    const int   RPP = (R + 255) & ~255;
    const int   CPP = (C + 255) & ~255;
    const float a_in = p / (float)nt, a_last = 1.0f - p;
    const float b_in = (1.0f - p) / (float)nc, b_last = p;

    // ---------------- A1: gather 8 timesteps as bf16 hi/lo + squared norms ----------------
    for (int job = gw; job < SPG * N_; job += GW) {
        int s = grp * SPG + (job >> 12);
        int r = job & (N_ - 1);
        int src = permg[r];
        const float4* sp = (const float4*)(X + ((size_t)src * S_ + s) * D_);
        float4 vv = sp[lane];
        __nv_bfloat16 h0 = __float2bfloat16_rn(vv.x);
        __nv_bfloat16 h1 = __float2bfloat16_rn(vv.y);
        __nv_bfloat16 h2 = __float2bfloat16_rn(vv.z);
        __nv_bfloat16 h3 = __float2bfloat16_rn(vv.w);
        __nv_bfloat16 l0 = __float2bfloat16_rn(vv.x - __bfloat162float(h0));
        __nv_bfloat16 l1 = __float2bfloat16_rn(vv.y - __bfloat162float(h1));
        __nv_bfloat16 l2 = __float2bfloat16_rn(vv.z - __bfloat162float(h2));
        __nv_bfloat16 l3 = __float2bfloat16_rn(vv.w - __bfloat162float(h3));
        size_t off = ((size_t)s * N_ + r) * D_ + lane * 4;
        union { __nv_bfloat16 b[4]; uint2 u; } ph, pl;
        ph.b[0] = h0; ph.b[1] = h1; ph.b[2] = h2; ph.b[3] = h3;
        pl.b[0] = l0; pl.b[1] = l1; pl.b[2] = l2; pl.b[3] = l3;
        *(uint2*)(g_Xh + off) = ph.u;
        *(uint2*)(g_Xl + off) = pl.u;
        float sq = vv.x*vv.x + vv.y*vv.y + vv.z*vv.z + vv.w*vv.w;
        sq = warpSumF(sq);
        if (lane == 0) g_nrm[s * N_ + r] = sq;
    }
    GBAR();

    // ---------------- prologue: B blocks compute GEMM for step 0 ----------------
    {
        const int s0 = grp * SPG;
        if (!isA) {
            gemm_step(g_Xh + (size_t)s0 * N_ * D_, g_Xl + (size_t)s0 * N_ * D_,
                      g_nrm + s0 * N_, Mbuf0, nt, nc, CPP, lbB,
                      tid, lane, wid, Ah, Al, Bh, Bl, s_f, s_d,
                      &g_pmax[grp][lbB], &g_psum[grp][lbB]);
        }
    }
    GBAR();

    // ================== per-timestep loop ==================
    for (int sl = 0; sl < SPG; sl++) {
        const int s = grp * SPG + sl;
        float* Mg = (sl & 1) ? Mbuf1 : Mbuf0;
        float* Mnext = (sl & 1) ? Mbuf0 : Mbuf1;

        // ---------- B2: reduce ANB GEMM partials (all blocks, fixed order) ----------
        if (tid == 0) {
            float  dmax = -FLT_MAX;
            double dsum = 0.0;
            #pragma unroll 6
            for (int k2 = 0; k2 < ANB; k2++) {
                dmax = fmaxf(dmax, __ldcg(&g_pmax[grp][k2]));
                dsum += __ldcg(&g_psum[grp][k2]);
            }
            s_delta  = dmax;
            s_efflam = (float)(((double)nt * (double)nc) / dsum);
        }
        __syncthreads();
        const float delta  = s_delta;
        const float efflam = s_efflam;

        // ---------- B3: K = exp(-efflam*Mt)+eps (fp16, segment-permuted) + K^T (all 36) ----------
        {
            const int rowStrips = RPP >> 5, colStrips = CPP >> 7;
            const int nStr = rowStrips * colStrips;
            const int srow = wid;
            const int tj = tid >> 3;
            const int io = (tid & 7) * 4;
            const float kdelta = fast_exp(-efflam * delta) + EPSK;

            for (int str = lb; str < nStr; str += GNB) {
                int sr = str / colStrips, sc = str - sr * colStrips;
                int i0 = sr << 5, j0 = sc << 7;
                int i = i0 + srow;
                float kq[4];
                #pragma unroll
                for (int q = 0; q < 4; q++) {
                    int j = j0 + lane * 4 + q;
                    float kv;
                    if (i < nt && j < nc) {
                        float m = __ldcg(&Mg[(size_t)i * CPP + j]);
                        kv = fast_exp(-efflam * m) + EPSK;
                    } else if (i == nt && j < nc) kv = kdelta;
                    else if (j == nc && i < nt)   kv = kdelta;
                    else if (i == nt && j == nc)  kv = 1.0f + EPSK;
                    else                          kv = 0.0f;
                    kq[q] = kv;
                }
                *(float4*)&sh[srow * 132 + lane * 4] = make_float4(kq[0], kq[1], kq[2], kq[3]);
                {
                    union { __half2 h[2]; uint2 u; } cv;
                    cv.h[0] = __floats2half2_rn(kq[0], kq[1]);
                    cv.h[1] = __floats2half2_rn(kq[2], kq[3]);
                    int halfOff = (j0 & ~255) + lane * 8 + ((j0 & 128) ? 4 : 0);
                    *(uint2*)&Kg[(size_t)i * CPP + halfOff] = cv.u;
                }
                __syncthreads();
                {
                    union { __half2 h[2]; uint2 u; } cv;
                    cv.h[0] = __floats2half2_rn(sh[(io+0)*132 + tj], sh[(io+1)*132 + tj]);
                    cv.h[1] = __floats2half2_rn(sh[(io+2)*132 + tj], sh[(io+3)*132 + tj]);
                    int ii = i0 + io;
                    int halfOff = (ii & ~255) + ((ii & 127) >> 2) * 8 + ((ii & 128) ? 4 : 0);
                    *(uint2*)&KTg[(size_t)(j0 + tj) * RPP + halfOff] = cv.u;
                }
                __syncthreads();
            }
            if (lb == 0) {
                for (int r2 = tid; r2 < RPP; r2 += NT)
                    ug[r2] = (r2 < nt) ? a_in : ((r2 == nt) ? a_last : 0.0f);
                for (int c2 = tid; c2 < CPP; c2 += NT)
                    if (c2 >= C) bvg[c2] = 0.0f;
            }
        }
        GBAR();

        // ---------- split phase: A = Sinkhorn(s); B = GEMM(s+1) ----------
        const int segU = RPP >> 8;
        const int segB = CPP >> 8;
        const float4* ug4  = (const float4*)ug;
        const float4* bvg4 = (const float4*)bvg;

        if (isA) {
            const int cb4 = jid * 4;
            const int rb4 = jid * 4;
            for (int it = 0; it <= ITS; it++) {
                // pass1: bv = b / (K^T u)
                for (int i4 = tid; i4 < (RPP >> 2); i4 += NT)
                    ((float4*)sh)[i4] = __ldcg(ug4 + i4);
                __syncthreads();
                if (cb4 < C) {
                    float s0, s1, s2, s3;
                    dot4rows(KTg, RPP, cb4, sh, segU, lane, s0, s1, s2, s3);
                    if (lane == 0) {
                        bvg[cb4] = ((cb4 < nc) ? b_in : b_last) / s0;
                        if (cb4 + 1 < C) bvg[cb4 + 1] = ((cb4 + 1 < nc) ? b_in : b_last) / s1;
                        if (cb4 + 2 < C) bvg[cb4 + 2] = ((cb4 + 2 < nc) ? b_in : b_last) / s2;
                        if (cb4 + 3 < C) bvg[cb4 + 3] = ((cb4 + 3 < nc) ? b_in : b_last) / s3;
                    }
                }
                ABAR();
                if (it == ITS) break;

                // pass2: u = a / (K bv)
                for (int i4 = tid; i4 < (CPP >> 2); i4 += NT)
                    ((float4*)sh)[i4] = __ldcg(bvg4 + i4);
                __syncthreads();
                if (rb4 < R) {
                    float s0, s1, s2, s3;
                    dot4rows(Kg, CPP, rb4, sh, segB, lane, s0, s1, s2, s3);
                    if (lane == 0) {
                        ug[rb4] = ((rb4 < nt) ? a_in : a_last) / s0;
                        if (rb4 + 1 < R) ug[rb4 + 1] = ((rb4 + 1 < nt) ? a_in : a_last) / s1;
                        if (rb4 + 2 < R) ug[rb4 + 2] = ((rb4 + 2 < nt) ? a_in : a_last) / s2;
                        if (rb4 + 3 < R) ug[rb4 + 3] = ((rb4 + 3 < nt) ? a_in : a_last) / s3;
                    }
                }
                ABAR();
            }
        } else {
            if (sl + 1 < SPG) {
                const int sn = s + 1;
                gemm_step(g_Xh + (size_t)sn * N_ * D_, g_Xl + (size_t)sn * N_ * D_,
                          g_nrm + sn * N_, Mnext, nt, nc, CPP, lbB,
                          tid, lane, wid, Ah, Al, Bh, Bl, s_f, s_d,
                          &g_pmax[grp][lbB], &g_psum[grp][lbB]);
            }
        }
        GBAR();

        // ---------- final: 2 * sum u_i K_ij v_j Mt_ij (all 36 blocks) ----------
        {
            for (int i4 = tid; i4 < (CPP >> 2); i4 += NT)
                ((float4*)sh)[i4] = __ldcg(bvg4 + i4);
            __syncthreads();
            double wacc = 0.0;
            for (int r2 = gw; r2 < R; r2 += GW) {
                const uint4*  Kr = (const uint4*)(Kg + (size_t)r2 * CPP);
                const float4* Mr = (const float4*)(Mg + (size_t)r2 * CPP);
                const bool lastRow = (r2 == nt);
                float acc = 0.0f;
                for (int sg = 0; sg < segB; sg++) {
                    uint4 kv = __ldcg(Kr + sg * 32 + lane);
                    const __half2* hp = (const __half2*)&kv;
                    float4 m0 = __ldcg(Mr + sg * 64 + lane);
                    float4 m1 = __ldcg(Mr + sg * 64 + 32 + lane);
                    float4 vv0 = *(const float4*)&sh[sg * 256 + lane * 4];
                    float4 vv1 = *(const float4*)&sh[sg * 256 + 128 + lane * 4];
                    float2 f0 = __half22float2(hp[0]);
                    float2 f1 = __half22float2(hp[1]);
                    float2 f2 = __half22float2(hp[2]);
                    float2 f3 = __half22float2(hp[3]);
                    int j1 = sg * 256 + lane * 4;
                    int j2 = j1 + 128;
                    float mt[8];
                    if (lastRow) {
                        mt[0] = (j1+0 < nc) ? delta : 0.0f;
                        mt[1] = (j1+1 < nc) ? delta : 0.0f;
                        mt[2] = (j1+2 < nc) ? delta : 0.0f;
                        mt[3] = (j1+3 < nc) ? delta : 0.0f;
                        mt[4] = (j2+0 < nc) ? delta : 0.0f;
                        mt[5] = (j2+1 < nc) ? delta : 0.0f;
                        mt[6] = (j2+2 < nc) ? delta : 0.0f;
                        mt[7] = (j2+3 < nc) ? delta : 0.0f;
                    } else {
                        mt[0] = (j1+0 < nc) ? m0.x : ((j1+0 == nc) ? delta : 0.0f);
                        mt[1] = (j1+1 < nc) ? m0.y : ((j1+1 == nc) ? delta : 0.0f);
                        mt[2] = (j1+2 < nc) ? m0.z : ((j1+2 == nc) ? delta : 0.0f);
                        mt[3] = (j1+3 < nc) ? m0.w : ((j1+3 == nc) ? delta : 0.0f);
                        mt[4] = (j2+0 < nc) ? m1.x : ((j2+0 == nc) ? delta : 0.0f);
                        mt[5] = (j2+1 < nc) ? m1.y : ((j2+1 == nc) ? delta : 0.0f);
                        mt[6] = (j2+2 < nc) ? m1.z : ((j2+2 == nc) ? delta : 0.0f);
                        mt[7] = (j2+3 < nc) ? m1.w : ((j2+3 == nc) ? delta : 0.0f);
                    }
                    acc = fmaf(f0.x * vv0.x, mt[0], acc);
                    acc = fmaf(f0.y * vv0.y, mt[1], acc);
                    acc = fmaf(f1.x * vv0.z, mt[2], acc);
                    acc = fmaf(f1.y * vv0.w, mt[3], acc);
                    acc = fmaf(f2.x * vv1.x, mt[4], acc);
                    acc = fmaf(f2.y * vv1.y, mt[5], acc);
                    acc = fmaf(f3.x * vv1.z, mt[6], acc);
                    acc = fmaf(f3.y * vv1.w, mt[7], acc);
                }
                acc = warpSumF(acc);
                if (lane == 0) wacc += (double)(__ldcg(&ug[r2]) * acc);
            }
            __syncthreads();
            if (lane == 0) s_d[wid] = wacc;
            __syncthreads();
            if (wid == 0) {
                double t2 = warpSumD(s_d[lane]);
                if (lane == 0) g_pres[grp][lb] = t2;
            }
        }
        GBAR();
        if (lb == 0 && tid == 0) {
            double ts = 0.0;
            #pragma unroll 6
            for (int k2 = 0; k2 < GNB; k2++) ts += __ldcg(&g_pres[grp][k2]);
            g_res[s] = 2.0 * ts;
        }
    }

    // ---------------- global combine ----------------
    __threadfence();
    __syncthreads();
    if (tid == 0) atomicAdd(&g_doneCnt, 1ULL);
    if (bid == 0 && tid == 0) {
        unsigned long long tgt = doneBase + (unsigned long long)NB;
        while (*(volatile unsigned long long*)&g_doneCnt < tgt) { __nanosleep(128); }
        __threadfence();
        double total = 0.0;
        for (int s = 0; s < S_; s++) total += __ldcg(&g_res[s]);
        out[0] = (float)total;
    }
}

extern "C" void kernel_launch(void* const* d_in, const int* in_sizes, int n_in,
                              void* d_out, int out_size) {
    const float* X = (const float*)d_in[0];
    const int*   T = (const int*)d_in[1];
    float* out = (float*)d_out;
    (void)in_sizes; (void)n_in; (void)out_size;
    cudaFuncSetAttribute(sinkhorn_all, cudaFuncAttributeMaxDynamicSharedMemorySize, SMEM_BYTES);
    sinkhorn_all<<<NB, NT, SMEM_BYTES>>>(X, T, out);
}

// round 13
// speedup vs baseline: 1.2400x; 1.2400x over previous
#include <cuda_runtime.h>
#include <cuda_fp16.h>
#include <cuda_bf16.h>
#include <math.h>
#include <float.h>

#define NB 144          // total blocks (1 CTA/SM, 144 <= 148)
#define GROUPS 4        // independent groups
#define GNB 36          // blocks per group
#define SPG 8           // timesteps per group
#define NT 1024         // threads per block
#define N_ 4096
#define S_ 32
#define D_ 128
#define MAXP 4352       // worst-case padded dim (multiple of 256)
#define ITS 20
#define EPSK 1e-6f
#define LDH 72          // padded smem row stride in halves
#define SMEM_BYTES 36864   // 2 tiles x 128 rows x 72 halves x 2B

// ---------------- persistent scratch ----------------
__device__ __align__(16) __nv_bfloat16 g_Xb[(size_t)S_ * N_ * D_];   // bf16 permuted X
__device__ float  g_nrm[S_ * N_];
__device__ __align__(16) __nv_bfloat16 g_M [(size_t)GROUPS * MAXP * MAXP];  // bf16 cost matrix
__device__ __align__(16) __half g_K [(size_t)GROUPS * MAXP * MAXP];
__device__ __align__(16) __half g_KT[(size_t)GROUPS * MAXP * MAXP];
__device__ __align__(16) float  g_u [GROUPS][MAXP];
__device__ __align__(16) float  g_bv[GROUPS][MAXP];
__device__ int    g_perm[GROUPS][N_];
__device__ int    g_ntA [GROUPS];
__device__ float  g_pA  [GROUPS];
__device__ float  g_pmax[GROUPS][GNB];
__device__ double g_psum[GROUPS][GNB];
__device__ double g_pres[GROUPS][GNB];
__device__ double g_res [S_];
__device__ unsigned long long g_barCnt[GROUPS * 16];
__device__ unsigned long long g_doneCnt;

// ---------------- group barrier: monotonic counter, tight poll ----------------
__device__ __forceinline__ void gbar_sync(unsigned long long* cnt, unsigned long long tgt) {
    __syncthreads();
    if (threadIdx.x == 0) {
        __threadfence();
        atomicAdd(cnt, 1ULL);
        while (*(volatile unsigned long long*)cnt < tgt) { }
        __threadfence();
    }
    __syncthreads();
}
#define GBAR() do { ++barK; gbar_sync(cntp, barBase + (unsigned long long)barK * GNB); } while (0)

// ---------------- FFMA-only expf ----------------
__device__ __forceinline__ float fast_exp(float x) {
    const float L2E = 1.4426950408889634f;
    float y = fmaf(x, L2E, 12582912.0f);
    int   n = __float_as_int(y) - 0x4B400000;
    float r = y - 12582912.0f;
    float f = fmaf(x, L2E, -r);
    float p =        1.540353040e-4f;
    p = fmaf(p, f,   1.333355815e-3f);
    p = fmaf(p, f,   9.618129107e-3f);
    p = fmaf(p, f,   5.550410866e-2f);
    p = fmaf(p, f,   2.402265070e-1f);
    p = fmaf(p, f,   6.931471806e-1f);
    p = fmaf(p, f,   1.0f);
    return p * __int_as_float((n + 127) << 23);
}

__device__ __forceinline__ float warpMaxF(float v) {
    #pragma unroll
    for (int o = 16; o; o >>= 1) v = fmaxf(v, __shfl_down_sync(0xffffffffu, v, o));
    return v;
}
__device__ __forceinline__ float warpSumF(float v) {
    #pragma unroll
    for (int o = 16; o; o >>= 1) v += __shfl_down_sync(0xffffffffu, v, o);
    return v;
}
__device__ __forceinline__ double warpSumD(double v) {
    #pragma unroll
    for (int o = 16; o; o >>= 1) v += __shfl_down_sync(0xffffffffu, v, o);
    return v;
}
__device__ __forceinline__ void warpSum2F(float& v0, float& v1) {
    #pragma unroll
    for (int o = 16; o; o >>= 1) {
        v0 += __shfl_down_sync(0xffffffffu, v0, o);
        v1 += __shfl_down_sync(0xffffffffu, v1, o);
    }
}

// ---------------- mma.sync m16n8k16 bf16 (fp32 accum) ----------------
__device__ __forceinline__ void mma16816(float& c0, float& c1, float& c2, float& c3,
                                         unsigned a0, unsigned a1, unsigned a2, unsigned a3,
                                         unsigned b0, unsigned b1) {
    asm volatile("mma.sync.aligned.m16n8k16.row.col.f32.bf16.bf16.f32 "
        "{%0,%1,%2,%3}, {%4,%5,%6,%7}, {%8,%9}, {%0,%1,%2,%3};"
        : "+f"(c0), "+f"(c1), "+f"(c2), "+f"(c3)
        : "r"(a0), "r"(a1), "r"(a2), "r"(a3), "r"(b0), "r"(b1));
}

__global__ void __launch_bounds__(NT, 1)
sinkhorn_all(const float* __restrict__ X, const int* __restrict__ T, float* __restrict__ out)
{
    extern __shared__ __align__(16) char smraw[];
    float* sh = (float*)smraw;
    __nv_bfloat16* Ah = (__nv_bfloat16*)smraw;          // 128 x LDH
    __nv_bfloat16* Bh = Ah + 128 * LDH;                 // 128 x LDH

    __shared__ float  s_f[32];
    __shared__ double s_d[32];
    __shared__ float  s_delta, s_efflam;

    const int tid  = threadIdx.x;
    const int bid  = blockIdx.x;
    const int lane = tid & 31;
    const int wid  = tid >> 5;
    const int grp  = bid / GNB;
    const int lb   = bid - grp * GNB;
    const int gw   = lb * 32 + wid;     // warp within group (0..1151)
    const int GW   = GNB * 32;

    unsigned long long* cntp = &g_barCnt[grp * 16];
    unsigned long long v0 = *(volatile unsigned long long*)cntp;
    unsigned long long barBase = v0 - (v0 % (unsigned long long)GNB);
    int barK = 0;

    unsigned long long doneBase = 0;
    if (bid == 0 && tid == 0) {
        unsigned long long dv = *(volatile unsigned long long*)&g_doneCnt;
        doneBase = dv - (dv % (unsigned long long)NB);
    }

    __nv_bfloat16* Mg = g_M + (size_t)grp * MAXP * MAXP;
    __half* Kg  = g_K  + (size_t)grp * MAXP * MAXP;
    __half* KTg = g_KT + (size_t)grp * MAXP * MAXP;
    float*  ug  = g_u [grp];
    float*  bvg = g_bv[grp];
    int*    permg = g_perm[grp];

    // ---------------- A0: stable permutation (per group) ----------------
    if (lb == 0) {
        int* cnt = (int*)sh;
        int base = tid * 4;
        int tv0 = T[base], tv1 = T[base+1], tv2 = T[base+2], tv3 = T[base+3];
        int c = (tv0 > 0) + (tv1 > 0) + (tv2 > 0) + (tv3 > 0);
        cnt[tid] = c;
        __syncthreads();
        for (int off = 1; off < NT; off <<= 1) {
            int vv  = cnt[tid];
            int add = (tid >= off) ? cnt[tid - off] : 0;
            __syncthreads();
            cnt[tid] = vv + add;
            __syncthreads();
        }
        int total = cnt[NT - 1];
        int excl  = cnt[tid] - c;
        int tpos = excl, cpos = total + base - excl;
        if (tv0 > 0) permg[tpos++] = base + 0; else permg[cpos++] = base + 0;
        if (tv1 > 0) permg[tpos++] = base + 1; else permg[cpos++] = base + 1;
        if (tv2 > 0) permg[tpos++] = base + 2; else permg[cpos++] = base + 2;
        if (tv3 > 0) permg[tpos++] = base + 3; else permg[cpos++] = base + 3;
        if (tid == NT - 1) { g_ntA[grp] = total; g_pA[grp] = (float)total / (float)N_; }
    }
    GBAR();

    const int   nt = g_ntA[grp];
    const int   nc = N_ - nt;
    const float p  = g_pA[grp];
    const int   R = nt + 1, C = nc + 1;
    const int   RPP = (R + 255) & ~255;
    const int   CPP = (C + 255) & ~255;
    const float a_in = p / (float)nt, a_last = 1.0f - p;
    const float b_in = (1.0f - p) / (float)nc, b_last = p;

    // ---------------- A1: gather 8 timesteps as bf16 + fp32 squared norms ----------------
    for (int job = gw; job < SPG * N_; job += GW) {
        int s = grp * SPG + (job >> 12);
        int r = job & (N_ - 1);
        int src = permg[r];
        const float4* sp = (const float4*)(X + ((size_t)src * S_ + s) * D_);
        float4 vv = sp[lane];
        union { __nv_bfloat16 b[4]; uint2 u; } ph;
        ph.b[0] = __float2bfloat16_rn(vv.x);
        ph.b[1] = __float2bfloat16_rn(vv.y);
        ph.b[2] = __float2bfloat16_rn(vv.z);
        ph.b[3] = __float2bfloat16_rn(vv.w);
        *(uint2*)(g_Xb + ((size_t)s * N_ + r) * D_ + lane * 4) = ph.u;
        float sq = vv.x*vv.x + vv.y*vv.y + vv.z*vv.z + vv.w*vv.w;
        sq = warpSumF(sq);
        if (lane == 0) g_nrm[s * N_ + r] = sq;
    }
    GBAR();

    // ================== per-timestep loop ==================
    for (int sl = 0; sl < SPG; sl++) {
        const int s = grp * SPG + sl;
        const float* nrm = g_nrm + s * N_;
        const __nv_bfloat16* Xbs = g_Xb + (size_t)s * N_ * D_;

        // ---------- B1: M = nx + ny - 2*X.X^T via single bf16 mma; store bf16 ----------
        {
            const int tilesI = (nt + 127) >> 7;
            const int tilesJ = (nc + 127) >> 7;
            const int nTiles = tilesI * tilesJ;
            const int wm = wid >> 2;          // 0..7
            const int wn = wid & 3;           // 0..3
            const int ldrow = tid >> 3;       // 0..127
            const int ldch  = tid & 7;        // 0..7
            float  lmax = -FLT_MAX;
            double lsum = 0.0;

            for (int tile = lb; tile < nTiles; tile += GNB) {
                int ti = tile / tilesJ, tj = tile - ti * tilesJ;
                int i0 = ti << 7, j0 = tj << 7;

                float acc[4][4];
                #pragma unroll
                for (int q = 0; q < 4; q++)
                    #pragma unroll
                    for (int c = 0; c < 4; c++) acc[q][c] = 0.0f;

                for (int kb = 0; kb < D_; kb += 64) {
                    __syncthreads();
                    {
                        int ar = i0 + ldrow; if (ar >= nt) ar = nt - 1;
                        int br = j0 + ldrow; if (br >= nc) br = nc - 1;
                        size_t aoff = (size_t)ar * D_ + kb + ldch * 8;
                        size_t boff = (size_t)(nt + br) * D_ + kb + ldch * 8;
                        int sm = ldrow * LDH + ldch * 8;
                        *(uint4*)&Ah[sm] = *(const uint4*)(Xbs + aoff);
                        *(uint4*)&Bh[sm] = *(const uint4*)(Xbs + boff);
                    }
                    __syncthreads();
                    #pragma unroll
                    for (int ks = 0; ks < 4; ks++) {
                        const int arow = wm * 16 + (lane >> 2);
                        const int ac   = ks * 16 + (lane & 3) * 2;
                        unsigned ah0 = *(const unsigned*)&Ah[arow * LDH + ac];
                        unsigned ah1 = *(const unsigned*)&Ah[(arow + 8) * LDH + ac];
                        unsigned ah2 = *(const unsigned*)&Ah[arow * LDH + ac + 8];
                        unsigned ah3 = *(const unsigned*)&Ah[(arow + 8) * LDH + ac + 8];
                        #pragma unroll
                        for (int q = 0; q < 4; q++) {
                            const int bn = wn * 32 + q * 8 + (lane >> 2);
                            unsigned bh0 = *(const unsigned*)&Bh[bn * LDH + ac];
                            unsigned bh1 = *(const unsigned*)&Bh[bn * LDH + ac + 8];
                            mma16816(acc[q][0], acc[q][1], acc[q][2], acc[q][3],
                                     ah0, ah1, ah2, ah3, bh0, bh1);
                        }
                    }
                }

                // epilogue: M = nx + ny - 2*dot -> bf16; stats from the stored values
                float tsum = 0.0f;
                const int er0 = i0 + wm * 16 + (lane >> 2);
                #pragma unroll
                for (int half = 0; half < 2; half++) {
                    const int rr = er0 + half * 8;
                    if (rr >= nt) continue;
                    const float nx = nrm[rr];
                    __nv_bfloat16* Mrow = Mg + (size_t)rr * CPP;
                    #pragma unroll
                    for (int q = 0; q < 4; q++) {
                        const int cc = j0 + wn * 32 + q * 8 + (lane & 3) * 2;
                        const float d0 = acc[q][half * 2 + 0];
                        const float d1 = acc[q][half * 2 + 1];
                        if (cc + 1 < nc) {
                            float m0 = fmaf(-2.0f, d0, nx + nrm[nt + cc]);
                            float m1 = fmaf(-2.0f, d1, nx + nrm[nt + cc + 1]);
                            __nv_bfloat162 mb = __floats2bfloat162_rn(m0, m1);
                            *(__nv_bfloat162*)(Mrow + cc) = mb;
                            float2 mr = __bfloat1622float2(mb);
                            lmax = fmaxf(lmax, fmaxf(mr.x, mr.y));
                            tsum += mr.x + mr.y;
                        } else if (cc < nc) {
                            float m0 = fmaf(-2.0f, d0, nx + nrm[nt + cc]);
                            __nv_bfloat16 mb = __float2bfloat16_rn(m0);
                            Mrow[cc] = mb;
                            float mr = __bfloat162float(mb);
                            lmax = fmaxf(lmax, mr);
                            tsum += mr;
                        }
                    }
                }
                lsum += (double)tsum;
            }
            lmax = warpMaxF(lmax);
            lsum = warpSumD(lsum);
            __syncthreads();
            if (lane == 0) { s_f[wid] = lmax; s_d[wid] = lsum; }
            __syncthreads();
            if (wid == 0) {
                float  m2 = s_f[lane];
                double s2 = s_d[lane];
                m2 = warpMaxF(m2);
                s2 = warpSumD(s2);
                if (lane == 0) { g_pmax[grp][lb] = m2; g_psum[grp][lb] = s2; }
            }
        }
        GBAR();

        // ---------- B2: reduce GNB partials (identical fixed order) ----------
        if (tid == 0) {
            float  dmax = -FLT_MAX;
            double dsum = 0.0;
            #pragma unroll 6
            for (int k2 = 0; k2 < GNB; k2++) {
                dmax = fmaxf(dmax, __ldcg(&g_pmax[grp][k2]));
                dsum += __ldcg(&g_psum[grp][k2]);
            }
            s_delta  = dmax;
            s_efflam = (float)(((double)nt * (double)nc) / dsum);
        }
        __syncthreads();
        const float delta  = s_delta;
        const float efflam = s_efflam;

        // ---------- B3: K = exp(-efflam*Mt)+eps (fp16, segment-permuted), K^T transpose ----------
        {
            const int rowStrips = RPP >> 5, colStrips = CPP >> 7;
            const int nStr = rowStrips * colStrips;
            const int srow = wid;
            const int tj = tid >> 3;
            const int io = (tid & 7) * 4;
            const float kdelta = fast_exp(-efflam * delta) + EPSK;

            for (int str = lb; str < nStr; str += GNB) {
                int sr = str / colStrips, sc = str - sr * colStrips;
                int i0 = sr << 5, j0 = sc << 7;
                int i = i0 + srow;
                float kq[4];
                if (i < nt && j0 + 127 < nc) {
                    uint2 mw = __ldcg((const uint2*)(Mg + (size_t)i * CPP + j0 + lane * 4));
                    float2 ma = __bfloat1622float2(*(const __nv_bfloat162*)&mw.x);
                    float2 mb = __bfloat1622float2(*(const __nv_bfloat162*)&mw.y);
                    kq[0] = fast_exp(-efflam * ma.x) + EPSK;
                    kq[1] = fast_exp(-efflam * ma.y) + EPSK;
                    kq[2] = fast_exp(-efflam * mb.x) + EPSK;
                    kq[3] = fast_exp(-efflam * mb.y) + EPSK;
                } else {
                    #pragma unroll
                    for (int q = 0; q < 4; q++) {
                        int j = j0 + lane * 4 + q;
                        float kv;
                        if (i < nt && j < nc) {
                            float m = __bfloat162float(Mg[(size_t)i * CPP + j]);
                            kv = fast_exp(-efflam * m) + EPSK;
                        } else if (i == nt && j < nc) kv = kdelta;
                        else if (j == nc && i < nt)   kv = kdelta;
                        else if (i == nt && j == nc)  kv = 1.0f + EPSK;
                        else                          kv = 0.0f;
                        kq[q] = kv;
                    }
                }
                *(float4*)&sh[srow * 132 + lane * 4] = make_float4(kq[0], kq[1], kq[2], kq[3]);
                {
                    union { __half2 h[2]; uint2 u; } cv;
                    cv.h[0] = __floats2half2_rn(kq[0], kq[1]);
                    cv.h[1] = __floats2half2_rn(kq[2], kq[3]);
                    int halfOff = (j0 & ~255) + lane * 8 + ((j0 & 128) ? 4 : 0);
                    *(uint2*)&Kg[(size_t)i * CPP + halfOff] = cv.u;
                }
                __syncthreads();
                {
                    union { __half2 h[2]; uint2 u; } cv;
                    cv.h[0] = __floats2half2_rn(sh[(io+0)*132 + tj], sh[(io+1)*132 + tj]);
                    cv.h[1] = __floats2half2_rn(sh[(io+2)*132 + tj], sh[(io+3)*132 + tj]);
                    int ii = i0 + io;
                    int halfOff = (ii & ~255) + ((ii & 127) >> 2) * 8 + ((ii & 128) ? 4 : 0);
                    *(uint2*)&KTg[(size_t)(j0 + tj) * RPP + halfOff] = cv.u;
                }
                __syncthreads();
            }
            if (lb == 0) {
                for (int r2 = tid; r2 < RPP; r2 += NT)
                    ug[r2] = (r2 < nt) ? a_in : ((r2 == nt) ? a_last : 0.0f);
                for (int c2 = tid; c2 < CPP; c2 += NT)
                    if (c2 >= C) bvg[c2] = 0.0f;
            }
        }
        GBAR();

        // ---------- Sinkhorn: 20 iterations + final v pass (2 rows/warp, R9 mapping) ----------
        const int segU = RPP >> 8;
        const int segB = CPP >> 8;
        const float4* ug4  = (const float4*)ug;
        const float4* bvg4 = (const float4*)bvg;

        for (int it = 0; it <= ITS; it++) {
            // pass1: bv = b / (K^T u)
            for (int i4 = tid; i4 < (RPP >> 2); i4 += NT)
                ((float4*)sh)[i4] = __ldcg(ug4 + i4);
            __syncthreads();
            for (int cb = gw * 2; cb < C; cb += GW * 2) {
                const int c1 = (cb + 1 < C) ? (cb + 1) : cb;
                const uint4* Kr0 = (const uint4*)(KTg + (size_t)cb * RPP);
                const uint4* Kr1 = (const uint4*)(KTg + (size_t)c1 * RPP);
                float a00 = 0, a01 = 0, a10 = 0, a11 = 0;
                for (int sg = 0; sg < segU; sg++) {
                    uint4 k0 = __ldcg(Kr0 + sg * 32 + lane);
                    uint4 k1 = __ldcg(Kr1 + sg * 32 + lane);
                    float4 u0 = *(const float4*)&sh[sg * 256 + lane * 4];
                    float4 u1 = *(const float4*)&sh[sg * 256 + 128 + lane * 4];
                    const __half2* h0 = (const __half2*)&k0;
                    const __half2* h1 = (const __half2*)&k1;
                    float2 p00 = __half22float2(h0[0]), p01 = __half22float2(h0[1]);
                    float2 p02 = __half22float2(h0[2]), p03 = __half22float2(h0[3]);
                    float2 p10 = __half22float2(h1[0]), p11 = __half22float2(h1[1]);
                    float2 p12 = __half22float2(h1[2]), p13 = __half22float2(h1[3]);
                    a00 = fmaf(p00.x, u0.x, a00); a01 = fmaf(p00.y, u0.y, a01);
                    a00 = fmaf(p01.x, u0.z, a00); a01 = fmaf(p01.y, u0.w, a01);
                    a00 = fmaf(p02.x, u1.x, a00); a01 = fmaf(p02.y, u1.y, a01);
                    a00 = fmaf(p03.x, u1.z, a00); a01 = fmaf(p03.y, u1.w, a01);
                    a10 = fmaf(p10.x, u0.x, a10); a11 = fmaf(p10.y, u0.y, a11);
                    a10 = fmaf(p11.x, u0.z, a10); a11 = fmaf(p11.y, u0.w, a11);
                    a10 = fmaf(p12.x, u1.x, a10); a11 = fmaf(p12.y, u1.y, a11);
                    a10 = fmaf(p13.x, u1.z, a10); a11 = fmaf(p13.y, u1.w, a11);
                }
                float s0 = a00 + a01, s1 = a10 + a11;
                warpSum2F(s0, s1);
                if (lane == 0) {
                    bvg[cb] = ((cb < nc) ? b_in : b_last) / s0;
                    if (cb + 1 < C) bvg[cb + 1] = ((cb + 1 < nc) ? b_in : b_last) / s1;
                }
            }
            GBAR();
            if (it == ITS) break;

            // pass2: u = a / (K bv)
            for (int i4 = tid; i4 < (CPP >> 2); i4 += NT)
                ((float4*)sh)[i4] = __ldcg(bvg4 + i4);
            __syncthreads();
            for (int rb = gw * 2; rb < R; rb += GW * 2) {
                const int r1 = (rb + 1 < R) ? (rb + 1) : rb;
                const uint4* Kr0 = (const uint4*)(Kg + (size_t)rb * CPP);
                const uint4* Kr1 = (const uint4*)(Kg + (size_t)r1 * CPP);
                float a00 = 0, a01 = 0, a10 = 0, a11 = 0;
                for (int sg = 0; sg < segB; sg++) {
                    uint4 k0 = __ldcg(Kr0 + sg * 32 + lane);
                    uint4 k1 = __ldcg(Kr1 + sg * 32 + lane);
                    float4 u0 = *(const float4*)&sh[sg * 256 + lane * 4];
                    float4 u1 = *(const float4*)&sh[sg * 256 + 128 + lane * 4];
                    const __half2* h0 = (const __half2*)&k0;
                    const __half2* h1 = (const __half2*)&k1;
                    float2 p00 = __half22float2(h0[0]), p01 = __half22float2(h0[1]);
                    float2 p02 = __half22float2(h0[2]), p03 = __half22float2(h0[3]);
                    float2 p10 = __half22float2(h1[0]), p11 = __half22float2(h1[1]);
                    float2 p12 = __half22float2(h1[2]), p13 = __half22float2(h1[3]);
                    a00 = fmaf(p00.x, u0.x, a00); a01 = fmaf(p00.y, u0.y, a01);
                    a00 = fmaf(p01.x, u0.z, a00); a01 = fmaf(p01.y, u0.w, a01);
                    a00 = fmaf(p02.x, u1.x, a00); a01 = fmaf(p02.y, u1.y, a01);
                    a00 = fmaf(p03.x, u1.z, a00); a01 = fmaf(p03.y, u1.w, a01);
                    a10 = fmaf(p10.x, u0.x, a10); a11 = fmaf(p10.y, u0.y, a11);
                    a10 = fmaf(p11.x, u0.z, a10); a11 = fmaf(p11.y, u0.w, a11);
                    a10 = fmaf(p12.x, u1.x, a10); a11 = fmaf(p12.y, u1.y, a11);
                    a10 = fmaf(p13.x, u1.z, a10); a11 = fmaf(p13.y, u1.w, a11);
                }
                float s0 = a00 + a01, s1 = a10 + a11;
                warpSum2F(s0, s1);
                if (lane == 0) {
                    ug[rb] = ((rb < nt) ? a_in : a_last) / s0;
                    if (rb + 1 < R) ug[rb + 1] = ((rb + 1 < nt) ? a_in : a_last) / s1;
                }
            }
            GBAR();
        }

        // ---------- Final: 2 * sum u_i K_ij v_j Mt_ij (M bf16) ----------
        {
            for (int i4 = tid; i4 < (CPP >> 2); i4 += NT)
                ((float4*)sh)[i4] = __ldcg(bvg4 + i4);
            __syncthreads();
            double wacc = 0.0;
            for (int r2 = gw; r2 < R; r2 += GW) {
                const uint4* Kr = (const uint4*)(Kg + (size_t)r2 * CPP);
                const __nv_bfloat16* Mr = Mg + (size_t)r2 * CPP;
                const bool lastRow = (r2 == nt);
                float acc = 0.0f;
                for (int sg = 0; sg < segB; sg++) {
                    uint4 kv = __ldcg(Kr + sg * 32 + lane);
                    const __half2* hp = (const __half2*)&kv;
                    int j1 = sg * 256 + lane * 4;
                    int j2 = j1 + 128;
                    float4 vv0 = *(const float4*)&sh[j1];
                    float4 vv1 = *(const float4*)&sh[j2];
                    float2 f0 = __half22float2(hp[0]);
                    float2 f1 = __half22float2(hp[1]);
                    float2 f2 = __half22float2(hp[2]);
                    float2 f3 = __half22float2(hp[3]);
                    float mt[8];
                    if (lastRow) {
                        mt[0] = (j1+0 < nc) ? delta : 0.0f;
                        mt[1] = (j1+1 < nc) ? delta : 0.0f;
                        mt[2] = (j1+2 < nc) ? delta : 0.0f;
                        mt[3] = (j1+3 < nc) ? delta : 0.0f;
                        mt[4] = (j2+0 < nc) ? delta : 0.0f;
                        mt[5] = (j2+1 < nc) ? delta : 0.0f;
                        mt[6] = (j2+2 < nc) ? delta : 0.0f;
                        mt[7] = (j2+3 < nc) ? delta : 0.0f;
                    } else {
                        uint2 mw0 = __ldcg((const uint2*)(Mr + j1));
                        uint2 mw1 = __ldcg((const uint2*)(Mr + j2));
                        float2 ma = __bfloat1622float2(*(const __nv_bfloat162*)&mw0.x);
                        float2 mb = __bfloat1622float2(*(const __nv_bfloat162*)&mw0.y);
                        float2 mc = __bfloat1622float2(*(const __nv_bfloat162*)&mw1.x);
                        float2 md = __bfloat1622float2(*(const __nv_bfloat162*)&mw1.y);
                        mt[0] = (j1+0 < nc) ? ma.x : ((j1+0 == nc) ? delta : 0.0f);
                        mt[1] = (j1+1 < nc) ? ma.y : ((j1+1 == nc) ? delta : 0.0f);
                        mt[2] = (j1+2 < nc) ? mb.x : ((j1+2 == nc) ? delta : 0.0f);
                        mt[3] = (j1+3 < nc) ? mb.y : ((j1+3 == nc) ? delta : 0.0f);
                        mt[4] = (j2+0 < nc) ? mc.x : ((j2+0 == nc) ? delta : 0.0f);
                        mt[5] = (j2+1 < nc) ? mc.y : ((j2+1 == nc) ? delta : 0.0f);
                        mt[6] = (j2+2 < nc) ? md.x : ((j2+2 == nc) ? delta : 0.0f);
                        mt[7] = (j2+3 < nc) ? md.y : ((j2+3 == nc) ? delta : 0.0f);
                    }
                    acc = fmaf(f0.x * vv0.x, mt[0], acc);
                    acc = fmaf(f0.y * vv0.y, mt[1], acc);
                    acc = fmaf(f1.x * vv0.z, mt[2], acc);
                    acc = fmaf(f1.y * vv0.w, mt[3], acc);
                    acc = fmaf(f2.x * vv1.x, mt[4], acc);
                    acc = fmaf(f2.y * vv1.y, mt[5], acc);
                    acc = fmaf(f3.x * vv1.z, mt[6], acc);
                    acc = fmaf(f3.y * vv1.w, mt[7], acc);
                }
                acc = warpSumF(acc);
                if (lane == 0) wacc += (double)(__ldcg(&ug[r2]) * acc);
            }
            __syncthreads();
            if (lane == 0) s_d[wid] = wacc;
            __syncthreads();
            if (wid == 0) {
                double t2 = warpSumD(s_d[lane]);
                if (lane == 0) g_pres[grp][lb] = t2;
            }
        }
        GBAR();
        if (lb == 0 && tid == 0) {
            double ts = 0.0;
            #pragma unroll 6
            for (int k2 = 0; k2 < GNB; k2++) ts += __ldcg(&g_pres[grp][k2]);
            g_res[s] = 2.0 * ts;
        }
    }

    // ---------------- global combine ----------------
    __threadfence();
    __syncthreads();
    if (tid == 0) atomicAdd(&g_doneCnt, 1ULL);
    if (bid == 0 && tid == 0) {
        unsigned long long tgt = doneBase + (unsigned long long)NB;
        while (*(volatile unsigned long long*)&g_doneCnt < tgt) { __nanosleep(128); }
        __threadfence();
        double total = 0.0;
        for (int s = 0; s < S_; s++) total += __ldcg(&g_res[s]);
        out[0] = (float)total;
    }
}

extern "C" void kernel_launch(void* const* d_in, const int* in_sizes, int n_in,
                              void* d_out, int out_size) {
    const float* X = (const float*)d_in[0];
    const int*   T = (const int*)d_in[1];
    float* out = (float*)d_out;
    (void)in_sizes; (void)n_in; (void)out_size;
    cudaFuncSetAttribute(sinkhorn_all, cudaFuncAttributeMaxDynamicSharedMemorySize, SMEM_BYTES);
    sinkhorn_all<<<NB, NT, SMEM_BYTES>>>(X, T, out);
}